// round 5
// baseline (speedup 1.0000x reference)
#include <cuda_runtime.h>
#include <cuda_bf16.h>
#include <math.h>

#define Bq 64
#define Hd 1024
#define Vv 32000
#define NSTEP 50
#define NLBLK 250      // 32000 / 128
#define KC 32          // logits k-chunk

typedef unsigned long long ull;

// ---------------- persistent device state (no allocation allowed) ----------
__device__ __align__(16) float g_hT[Hd * Bq];          // hidden, transposed [k][b]
__device__ __align__(16) float g_c[Bq * Hd];           // cell [b][k]
__device__ __align__(16) float g_gpart[2 * Bq * 4096]; // gate partial sums [z][b][n]
__device__ float g_pval[NLBLK * Bq];                   // per-block argmax partials
__device__ int   g_pidx[NLBLK * Bq];
__device__ int   g_tok[Bq];
__device__ int   g_active;

// ---------------- packed f32x2 helpers (Blackwell FFMA2) -------------------
__device__ __forceinline__ ull pack2(float lo, float hi) {
    ull r; asm("mov.b64 %0, {%1,%2};" : "=l"(r) : "f"(lo), "f"(hi)); return r;
}
__device__ __forceinline__ float2 unpack2(ull v) {
    float2 r; asm("mov.b64 {%0,%1}, %2;" : "=f"(r.x), "=f"(r.y) : "l"(v)); return r;
}
__device__ __forceinline__ void fma2(ull &d, ull a, ull b) {
    asm("fma.rn.f32x2 %0, %1, %2, %0;" : "+l"(d) : "l"(a), "l"(b));
}

// ---------------- init: transpose h, copy c, seed tokens -------------------
__global__ void k_init(const float* __restrict__ h_in, const float* __restrict__ c_in) {
    int b = blockIdx.x;
    for (int k = threadIdx.x; k < Hd; k += blockDim.x) {
        g_hT[k * Bq + b] = h_in[b * Hd + k];
        g_c[b * Hd + k]  = c_in[b * Hd + k];
    }
    if (b == 0) {
        if (threadIdx.x < Bq) g_tok[threadIdx.x] = 1;  // SOS
        if (threadIdx.x == 0) g_active = 1;
    }
}

// ---------------- gates GEMM (embedding gather fused) ----------------------
// grid (128, 2): x = n-block of 32 cols over n=g*1024+k; y = K-chunk of 512.
// 256 threads: tx=tid&31 -> column, ty=tid>>5 -> rowgroup of 8 batch rows.
// Each thread: 1 column, 8 rows = 4 f32x2 accumulators.
__global__ __launch_bounds__(256) void k_gates(const float* __restrict__ emb,
                                               const float* __restrict__ w_ih,
                                               const float* __restrict__ w_hh) {
    if (*(volatile int*)&g_active == 0) return;
    __shared__ __align__(16) float s_x[64 * 64];  // [kk][b]
    __shared__ __align__(16) float s_h[64 * 64];  // [kk][b]
    __shared__ int s_tok[Bq];

    int tid = threadIdx.x;
    if (tid < Bq) s_tok[tid] = g_tok[tid];
    __syncthreads();

    int tx = tid & 31, ty = tid >> 5;
    int n = blockIdx.x * 32 + tx;           // 0..4095
    int g = n >> 10, kcol = n & 1023;
    const float* wiP = w_ih + (size_t)g * Hd * Hd + kcol;
    const float* whP = w_hh + (size_t)g * Hd * Hd + kcol;
    int kbase = blockIdx.y * 512;

    ull acc[4] = {0ull, 0ull, 0ull, 0ull};

    for (int h0 = 0; h0 < 512; h0 += 64) {
        // ---- stage x tile (gather from emb rows) and h tile ----
        {
            int b = tid >> 2;
            const float* erow = emb + (size_t)s_tok[b] * Hd + kbase + h0;
#pragma unroll
            for (int j = 0; j < 4; j++) {
                int kk = ((tid & 3) + j * 4) * 4;
                float4 v = *(const float4*)(erow + kk);
                s_x[(kk + 0) * 64 + b] = v.x;
                s_x[(kk + 1) * 64 + b] = v.y;
                s_x[(kk + 2) * 64 + b] = v.z;
                s_x[(kk + 3) * 64 + b] = v.w;
            }
#pragma unroll
            for (int i = 0; i < 4; i++)
                *(float4*)(s_h + (tid + i * 256) * 4) =
                    *(const float4*)(g_hT + (kbase + h0) * Bq + (tid + i * 256) * 4);
        }
        __syncthreads();
        // ---- compute ----
#pragma unroll 8
        for (int k = 0; k < 64; k++) {
            size_t off = (size_t)(kbase + h0 + k) * Hd;
            float wi = wiP[off];
            float wh = whP[off];
            ull wi2 = pack2(wi, wi), wh2 = pack2(wh, wh);
            ulonglong2 Xa = *(const ulonglong2*)(s_x + k * 64 + ty * 8);
            ulonglong2 Xb = *(const ulonglong2*)(s_x + k * 64 + ty * 8 + 4);
            ulonglong2 Ha = *(const ulonglong2*)(s_h + k * 64 + ty * 8);
            ulonglong2 Hb = *(const ulonglong2*)(s_h + k * 64 + ty * 8 + 4);
            fma2(acc[0], Xa.x, wi2); fma2(acc[1], Xa.y, wi2);
            fma2(acc[2], Xb.x, wi2); fma2(acc[3], Xb.y, wi2);
            fma2(acc[0], Ha.x, wh2); fma2(acc[1], Ha.y, wh2);
            fma2(acc[2], Hb.x, wh2); fma2(acc[3], Hb.y, wh2);
        }
        __syncthreads();
    }

    float* dst = g_gpart + (size_t)blockIdx.y * Bq * 4096 + n;
    int r = ty * 8;
#pragma unroll
    for (int j = 0; j < 4; j++) {
        float2 p = unpack2(acc[j]);
        dst[(size_t)(r + 2 * j) * 4096]     = p.x;
        dst[(size_t)(r + 2 * j + 1) * 4096] = p.y;
    }
}

// ---------------- LSTM elementwise: commits h/c IN PLACE -------------------
__global__ void k_lstm(const float* __restrict__ b_ih, const float* __restrict__ b_hh) {
    if (*(volatile int*)&g_active == 0) return;
    int b = blockIdx.x;
    const float* p0 = g_gpart + (size_t)b * 4096;
    const float* p1 = g_gpart + (size_t)Bq * 4096 + (size_t)b * 4096;
    for (int k = threadIdx.x; k < Hd; k += blockDim.x) {
        float gi = p0[k]        + p1[k]        + b_ih[k]        + b_hh[k];
        float gf = p0[1024 + k] + p1[1024 + k] + b_ih[1024 + k] + b_hh[1024 + k];
        float gc = p0[2048 + k] + p1[2048 + k] + b_ih[2048 + k] + b_hh[2048 + k];
        float go = p0[3072 + k] + p1[3072 + k] + b_ih[3072 + k] + b_hh[3072 + k];
        float ig = 1.f / (1.f + expf(-gi));
        float fg = 1.f / (1.f + expf(-gf));
        float cg = tanhf(gc);
        float og = 1.f / (1.f + expf(-go));
        float cn = fg * g_c[b * Hd + k] + ig * cg;
        float hn = og * tanhf(cn);
        g_c[b * Hd + k]  = cn;
        g_hT[k * Bq + b] = hn;
    }
}

// ---------------- logits GEMM + fused per-block argmax ---------------------
// 250 blocks x 256 threads. Tile 64 rows x 128 cols. tx=col-group (4 cols),
// ty=rowgroup (8 rows). acc[col][rowpair]. Double-buffered smem.
__global__ __launch_bounds__(256, 2) void k_logits(const float* __restrict__ out_w,
                                                   const float* __restrict__ out_b,
                                                   const float* __restrict__ std_t) {
    if (*(volatile int*)&g_active == 0) return;
    __shared__ __align__(16) float s_w[2][KC * 128];  // [k][col]
    __shared__ __align__(16) float s_h[2][KC * 64];   // [k][b]
    int tid = threadIdx.x;
    int tx = tid & 31, ty = tid >> 5;
    int bc = blockIdx.x * 128;

    ull acc[4][4];
#pragma unroll
    for (int c = 0; c < 4; c++)
#pragma unroll
        for (int j = 0; j < 4; j++) acc[c][j] = 0ull;

    float4 rw[4], rh[2];
    // LDG chunk 0
#pragma unroll
    for (int i = 0; i < 4; i++) {
        int idx = tid + i * 256;
        rw[i] = *(const float4*)(out_w + (size_t)(idx >> 5) * Vv + bc + (idx & 31) * 4);
    }
#pragma unroll
    for (int i = 0; i < 2; i++)
        rh[i] = *(const float4*)(g_hT + (tid + i * 256) * 4);
    // STS chunk 0 -> buf 0
#pragma unroll
    for (int i = 0; i < 4; i++) *(float4*)(s_w[0] + (tid + i * 256) * 4) = rw[i];
#pragma unroll
    for (int i = 0; i < 2; i++) *(float4*)(s_h[0] + (tid + i * 256) * 4) = rh[i];
    // LDG chunk 1
#pragma unroll
    for (int i = 0; i < 4; i++) {
        int idx = tid + i * 256;
        rw[i] = *(const float4*)(out_w + (size_t)(KC + (idx >> 5)) * Vv + bc + (idx & 31) * 4);
    }
#pragma unroll
    for (int i = 0; i < 2; i++)
        rh[i] = *(const float4*)(g_hT + KC * 64 + (tid + i * 256) * 4);
    __syncthreads();

    const int nch = Hd / KC;  // 32
    for (int c = 0; c < nch; c++) {
        int buf = c & 1;
#pragma unroll 4
        for (int k = 0; k < KC; k++) {
            float4 wf = *(const float4*)(s_w[buf] + k * 128 + tx * 4);
            ulonglong2 A0 = *(const ulonglong2*)(s_h[buf] + k * 64 + ty * 8);
            ulonglong2 A1 = *(const ulonglong2*)(s_h[buf] + k * 64 + ty * 8 + 4);
            ull w2;
            w2 = pack2(wf.x, wf.x);
            fma2(acc[0][0], A0.x, w2); fma2(acc[0][1], A0.y, w2);
            fma2(acc[0][2], A1.x, w2); fma2(acc[0][3], A1.y, w2);
            w2 = pack2(wf.y, wf.y);
            fma2(acc[1][0], A0.x, w2); fma2(acc[1][1], A0.y, w2);
            fma2(acc[1][2], A1.x, w2); fma2(acc[1][3], A1.y, w2);
            w2 = pack2(wf.z, wf.z);
            fma2(acc[2][0], A0.x, w2); fma2(acc[2][1], A0.y, w2);
            fma2(acc[2][2], A1.x, w2); fma2(acc[2][3], A1.y, w2);
            w2 = pack2(wf.w, wf.w);
            fma2(acc[3][0], A0.x, w2); fma2(acc[3][1], A0.y, w2);
            fma2(acc[3][2], A1.x, w2); fma2(acc[3][3], A1.y, w2);
        }
        if (c + 1 < nch) {
            // STS prefetched chunk c+1 into other buffer (safe: last read of that
            // buffer finished before the syncthreads at end of iteration c-1)
#pragma unroll
            for (int i = 0; i < 4; i++) *(float4*)(s_w[buf ^ 1] + (tid + i * 256) * 4) = rw[i];
#pragma unroll
            for (int i = 0; i < 2; i++) *(float4*)(s_h[buf ^ 1] + (tid + i * 256) * 4) = rh[i];
            if (c + 2 < nch) {
#pragma unroll
                for (int i = 0; i < 4; i++) {
                    int idx = tid + i * 256;
                    rw[i] = *(const float4*)(out_w + (size_t)((c + 2) * KC + (idx >> 5)) * Vv
                                             + bc + (idx & 31) * 4);
                }
#pragma unroll
                for (int i = 0; i < 2; i++)
                    rh[i] = *(const float4*)(g_hT + (c + 2) * KC * 64 + (tid + i * 256) * 4);
            }
        }
        __syncthreads();
    }

    // epilogue: + out_b + std, per-row argmax. Warp (fixed ty) owns complete
    // rows ty*8..ty*8+7 across 128 cols -> warp-local reduction only.
    float4 obv = *(const float4*)(out_b + bc + tx * 4);
    const float* ob = (const float*)&obv;
#pragma unroll
    for (int j = 0; j < 4; j++) {
#pragma unroll
        for (int s = 0; s < 2; s++) {
            int r = ty * 8 + 2 * j + s;
            float4 sv = *(const float4*)(std_t + (size_t)r * Vv + bc + tx * 4);
            const float* sp = (const float*)&sv;
            float best = -1e30f;
            int bi = 0;
#pragma unroll
            for (int c = 0; c < 4; c++) {
                float2 p = unpack2(acc[c][j]);
                float val = (s ? p.y : p.x) + ob[c] + sp[c];
                int idx = bc + tx * 4 + c;
                if (val > best || (val == best && idx < bi)) { best = val; bi = idx; }
            }
#pragma unroll
            for (int o = 16; o > 0; o >>= 1) {
                float ov = __shfl_down_sync(0xffffffffu, best, o);
                int oi   = __shfl_down_sync(0xffffffffu, bi, o);
                if (ov > best || (ov == best && oi < bi)) { best = ov; bi = oi; }
            }
            if (tx == 0) {
                g_pval[blockIdx.x * Bq + r] = best;
                g_pidx[blockIdx.x * Bq + r] = bi;
            }
        }
    }
}

// ---------------- finalize argmax, token/active bookkeeping ----------------
__global__ void k_decide(float* __restrict__ out_tok, int write_tok) {
    __shared__ int s_max[2];
    int b = threadIdx.x;  // 64 threads
    int active = *(volatile int*)&g_active;
    float best = -1e30f;
    int bi = 0;
    if (active) {
#pragma unroll 10
        for (int blk = 0; blk < NLBLK; blk++) {
            float v = g_pval[blk * Bq + b];
            int   i = g_pidx[blk * Bq + b];
            if (v > best || (v == best && i < bi)) { best = v; bi = i; }
        }
        if (write_tok) out_tok[b] = (float)bi;
        g_tok[b] = bi;
    } else {
        if (write_tok) out_tok[b] = 0.0f;
    }
    int m = bi;
#pragma unroll
    for (int o = 16; o > 0; o >>= 1)
        m = max(m, __shfl_down_sync(0xffffffffu, m, o));
    if ((b & 31) == 0) s_max[b >> 5] = m;
    __syncthreads();
    if (b == 0 && active)
        g_active = (max(s_max[0], s_max[1]) > 0) ? 1 : 0;
}

// ---------------- write final hidden state ---------------------------------
__global__ void k_final(float* __restrict__ out_h) {
    int b = blockIdx.x;
    for (int k = threadIdx.x; k < Hd; k += blockDim.x)
        out_h[b * Hd + k] = g_hT[k * Bq + b];
}

// ---------------- launcher -------------------------------------------------
extern "C" void kernel_launch(void* const* d_in, const int* in_sizes, int n_in,
                              void* d_out, int out_size) {
    // inputs in setup_inputs order:
    // 0 encoder_output (unused), 1 std, 2 h, 3 c, 4 emb,
    // 5 w_ih, 6 w_hh, 7 b_ih, 8 b_hh, 9 out_w, 10 out_b
    const float* std_in = (const float*)d_in[1];
    const float* h_in   = (const float*)d_in[2];
    const float* c_in   = (const float*)d_in[3];
    const float* emb    = (const float*)d_in[4];
    const float* w_ih   = (const float*)d_in[5];
    const float* w_hh   = (const float*)d_in[6];
    const float* b_ih   = (const float*)d_in[7];
    const float* b_hh   = (const float*)d_in[8];
    const float* out_w  = (const float*)d_in[9];
    const float* out_b  = (const float*)d_in[10];
    float* out = (float*)d_out;

    // layout: tokens [50*64] then h [64*1024] (float32). Guard on out_size.
    int write_tok = (out_size >= NSTEP * Bq) ? 1 : 0;
    int write_h   = (out_size == Hd * Bq || out_size >= NSTEP * Bq + Hd * Bq) ? 1 : 0;
    int h_off     = (out_size >= NSTEP * Bq + Hd * Bq) ? NSTEP * Bq : 0;

    k_init<<<Bq, 256>>>(h_in, c_in);
    for (int t = 0; t < NSTEP; t++) {
        k_gates<<<dim3(128, 2), 256>>>(emb, w_ih, w_hh);
        k_lstm<<<Bq, 256>>>(b_ih, b_hh);
        k_logits<<<NLBLK, 256>>>(out_w, out_b, std_in + (size_t)t * Bq * Vv);
        k_decide<<<1, Bq>>>(out + (size_t)t * Bq, write_tok);
    }
    if (write_h) k_final<<<Bq, 256>>>(out + h_off);
}